// round 7
// baseline (speedup 1.0000x reference)
#include <cuda_runtime.h>
#include <cuda_bf16.h>

#define B_ 4
#define H_ 16
#define NQ 256
#define D_ 16

typedef unsigned long long u64;

#define ABSM 0x7FFFFFFF7FFFFFFFULL

// ---- packed f32x2 helpers (sm_100a) ---------------------------------------
__device__ __forceinline__ u64 pk(float a, float b) {
    u64 r; asm("mov.b64 %0, {%1,%2};" : "=l"(r) : "f"(a), "f"(b)); return r;
}
__device__ __forceinline__ void upk(u64 v, float& a, float& b) {
    asm("mov.b64 {%0,%1}, %2;" : "=f"(a), "=f"(b) : "l"(v));
}
__device__ __forceinline__ u64 fma2_(u64 a, u64 b, u64 c) {
    u64 r; asm("fma.rn.f32x2 %0, %1, %2, %3;" : "=l"(r) : "l"(a), "l"(b), "l"(c));
    return r;
}
__device__ __forceinline__ u64 add2_(u64 a, u64 b) {
    u64 r; asm("add.rn.f32x2 %0, %1, %2;" : "=l"(r) : "l"(a), "l"(b));
    return r;
}
__device__ __forceinline__ u64 mul2_(u64 a, u64 b) {
    u64 r; asm("mul.rn.f32x2 %0, %1, %2;" : "=l"(r) : "l"(a), "l"(b));
    return r;
}

// Scratch for projected Q/K/V in [b][h][n][d] layout.
__device__ float g_Q[B_ * H_ * NQ * D_];
__device__ float g_K[B_ * H_ * NQ * D_];
__device__ float g_V[B_ * H_ * NQ * D_];

// ---------------------------------------------------------------------------
// Kernel A: QKV projections.  out[m, hd] = sum_e A[m, e] * W[hd, e]
// 512 threads/block (16 warps -> real latency hiding), tile 64x64,
// 2x4 micro-tile, K-step 16, double-buffered smem, packed-f32x2 inner.
// Staging split: threads 0-255 load A, 256-511 load W (1 float4 each / step).
// ---------------------------------------------------------------------------
__global__ __launch_bounds__(512) void qkv_kernel(
    const float* __restrict__ row_emb, const float* __restrict__ col_emb,
    const float* __restrict__ Wq, const float* __restrict__ Wk,
    const float* __restrict__ Wv)
{
    __shared__ float As[2][16][68];   // [stage][k][m], padded
    __shared__ float Ws[2][16][68];   // [stage][k][n], padded

    const float* A; const float* W; float* O;
    int z = blockIdx.z;
    if (z == 0)      { A = row_emb; W = Wq; O = g_Q; }
    else if (z == 1) { A = col_emb; W = Wk; O = g_K; }
    else             { A = col_emb; W = Wv; O = g_V; }

    int m0 = blockIdx.y * 64;
    int n0 = blockIdx.x * 64;
    int t  = threadIdx.x;
    int tx = t & 15;          // n-subtile: cols tx*4 .. tx*4+3
    int ty = t >> 4;          // 0..31: rows ty*2, ty*2+1

    bool loadA = t < 256;
    int u  = loadA ? t : t - 256;
    int lm = u >> 2, lk = (u & 3) * 4;
    const float* Sp = loadA ? &A[(m0 + lm) * 256 + lk]
                            : &W[(n0 + lm) * 256 + lk];

    u64 acc[2][2];
    acc[0][0] = acc[0][1] = acc[1][0] = acc[1][1] = 0ull;

    // Prologue: fill stage 0.
    {
        float4 v = *(const float4*)Sp;
        float (*S)[68] = loadA ? As[0] : Ws[0];
        S[lk + 0][lm] = v.x; S[lk + 1][lm] = v.y;
        S[lk + 2][lm] = v.z; S[lk + 3][lm] = v.w;
    }
    __syncthreads();

    for (int k0 = 0; k0 < 256; k0 += 16) {
        int cur = (k0 >> 4) & 1, nxt = cur ^ 1;
        float4 v;
        bool more = (k0 + 16) < 256;
        if (more) v = *(const float4*)(Sp + k0 + 16);
        #pragma unroll
        for (int k = 0; k < 16; k++) {
            float2 a2 = *(const float2*)&As[cur][k][ty * 2];
            float4 b4 = *(const float4*)&Ws[cur][k][tx * 4];
            u64 b01 = pk(b4.x, b4.y);
            u64 b23 = pk(b4.z, b4.w);
            u64 a0  = pk(a2.x, a2.x);
            u64 a1  = pk(a2.y, a2.y);
            acc[0][0] = fma2_(a0, b01, acc[0][0]);
            acc[0][1] = fma2_(a0, b23, acc[0][1]);
            acc[1][0] = fma2_(a1, b01, acc[1][0]);
            acc[1][1] = fma2_(a1, b23, acc[1][1]);
        }
        if (more) {
            float (*S)[68] = loadA ? As[nxt] : Ws[nxt];
            S[lk + 0][lm] = v.x; S[lk + 1][lm] = v.y;
            S[lk + 2][lm] = v.z; S[lk + 3][lm] = v.w;
            __syncthreads();
        }
    }

    int bb = m0 >> 8;
    int hh = (n0 >> 4) + (tx >> 2);
    int dd = (tx & 3) * 4;
    #pragma unroll
    for (int i = 0; i < 2; i++) {
        int r = (m0 + ty * 2 + i) & 255;
        float4 o;
        upk(acc[i][0], o.x, o.y);
        upk(acc[i][1], o.z, o.w);
        *(float4*)&O[((bb * H_ + hh) * NQ + r) * D_ + dd] = o;
    }
}

// ---------------------------------------------------------------------------
// Reduce-scatter over 32 lanes: input acc[8] packed u64 = 16 floats (d pairs).
// Returns full 32-lane sum for d = f(lane); every xor-1 lane pair agrees.
// ---------------------------------------------------------------------------
__device__ __forceinline__ float reduce16(const u64 acc[8], int lane, int& dOut)
{
    bool k16 = (lane & 16) == 0;
    u64 h[4];
    #pragma unroll
    for (int j = 0; j < 4; j++) {
        u64 send = k16 ? acc[4 + j] : acc[j];
        u64 recv = __shfl_xor_sync(0xffffffffu, send, 16);
        u64 mine = k16 ? acc[j] : acc[4 + j];
        h[j] = add2_(mine, recv);
    }
    bool k8 = (lane & 8) == 0;
    u64 g[2];
    #pragma unroll
    for (int j = 0; j < 2; j++) {
        u64 send = k8 ? h[2 + j] : h[j];
        u64 recv = __shfl_xor_sync(0xffffffffu, send, 8);
        u64 mine = k8 ? h[j] : h[2 + j];
        g[j] = add2_(mine, recv);
    }
    bool k4 = (lane & 4) == 0;
    {
        u64 send = k4 ? g[1] : g[0];
        u64 recv = __shfl_xor_sync(0xffffffffu, send, 4);
        u64 mine = k4 ? g[0] : g[1];
        g[0] = add2_(mine, recv);
    }
    float lo, hi; upk(g[0], lo, hi);
    bool k2 = (lane & 2) == 0;
    float send = k2 ? hi : lo;
    float recv = __shfl_xor_sync(0xffffffffu, send, 2);
    float s = (k2 ? lo : hi) + recv;
    s += __shfl_xor_sync(0xffffffffu, s, 1);
    dOut = ((lane & 16) >> 1) | ((lane & 8) >> 1) | ((lane & 4) >> 1) | ((lane & 2) >> 1);
    return s;
}

// ---------------------------------------------------------------------------
// Kernel B: fused scores + mixing-MLP + softmax + AV.
// One warp per TWO rows, fully row-pair packed: phase 1 is 128 fma2/warp
// using K duplicated in smem as (k,k) u64 pairs (conflict-free stride 18),
// q packed as (q0,q1).  dp/cp/score pairs all hold (row0,row1).
// Kdup buffer is reused for the V tile after phase 1 (sync-guarded).
// MLP identity: sum w2*relu(t) = A*dot + B*cost + [C] + sum (0.5w2)|t|,
// C and mix2_bias softmax-invariant (dropped); 1/sqrt(D) folded into w1a.
// ---------------------------------------------------------------------------
__global__ __launch_bounds__(256, 3) void attn_kernel(
    const float* __restrict__ cost_mat,
    const float* __restrict__ mix1_w,   // [16][2][32]
    const float* __restrict__ mix1_b,   // [16][32]
    const float* __restrict__ mix2_w,   // [16][32][1]
    float* __restrict__ out)            // [B][R][H*D]
{
    __shared__ __align__(16) char smem_raw[256 * 18 * 8];   // 36 KB union
    __shared__ u64 mlpp[32][4];        // (wx pair, wy pair, b1 pair, 0.5*w2 pair)
    __shared__ u64 ABs[2];             // packed (A,A), (B,B)

    u64   (*Kdup)[18] = reinterpret_cast<u64(*)[18]>(smem_raw);   // phase 1
    float (*Vs)[20]   = reinterpret_cast<float(*)[20]>(smem_raw); // phase 4

    int b = blockIdx.z, h = blockIdx.y, rt = blockIdx.x;
    int bh = b * H_ + h;
    int t = threadIdx.x;
    int lane = t & 31, w = t >> 5;
    int r0 = rt * 16 + w * 2;           // this warp handles rows r0, r0+1

    // ---- stage K duplicated: Kdup[c][d] = (K[c][d], K[c][d]) ----
    {
        const float* Kg = g_K + (bh * NQ + t) * D_;
        #pragma unroll
        for (int j = 0; j < 4; j++) {
            float4 k4 = *(const float4*)&Kg[j * 4];
            Kdup[t][j * 4 + 0] = pk(k4.x, k4.x);
            Kdup[t][j * 4 + 1] = pk(k4.y, k4.y);
            Kdup[t][j * 4 + 2] = pk(k4.z, k4.z);
            Kdup[t][j * 4 + 3] = pk(k4.w, k4.w);
        }
    }
    if (t < 32) {
        float wxv = mix1_w[h * 64 + t] * 0.25f;   // fold 1/sqrt(D)
        float wyv = mix1_w[h * 64 + 32 + t];
        float bzv = mix1_b[h * 32 + t];
        float hwv = mix2_w[h * 32 + t] * 0.5f;    // fold 0.5 of abs-relu identity
        mlpp[t][0] = pk(wxv, wxv);
        mlpp[t][1] = pk(wyv, wyv);
        mlpp[t][2] = pk(bzv, bzv);
        mlpp[t][3] = pk(hwv, hwv);
        float a  = hwv * wxv;
        float bb = hwv * wyv;
        #pragma unroll
        for (int o = 16; o; o >>= 1) {
            a  += __shfl_xor_sync(0xffffffffu, a, o);
            bb += __shfl_xor_sync(0xffffffffu, bb, o);
        }
        if (t == 0) { ABs[0] = pk(a, a); ABs[1] = pk(bb, bb); }
    }
    __syncthreads();

    // ---- Phase 1: packed dot scores, dp[i] = (dot_r0, dot_r1) for col i ----
    u64 qp[16];
    {
        const float* Qg = g_Q + (bh * NQ + r0) * D_;
        #pragma unroll
        for (int j = 0; j < 4; j++) {
            float4 a = *(const float4*)&Qg[j * 4];
            float4 c = *(const float4*)&Qg[16 + j * 4];
            qp[j * 4 + 0] = pk(a.x, c.x);
            qp[j * 4 + 1] = pk(a.y, c.y);
            qp[j * 4 + 2] = pk(a.z, c.z);
            qp[j * 4 + 3] = pk(a.w, c.w);
        }
    }
    u64 dp[8];
    #pragma unroll
    for (int i = 0; i < 8; i++) {
        int c = i * 32 + lane;
        u64 s = 0ull;
        #pragma unroll
        for (int j = 0; j < 8; j++) {
            ulonglong2 kk = *(const ulonglong2*)&Kdup[c][2 * j];
            s = fma2_(qp[2 * j],     kk.x, s);
            s = fma2_(qp[2 * j + 1], kk.y, s);
        }
        dp[i] = s;
    }
    __syncthreads();   // all warps done reading Kdup

    // ---- stage V into the same buffer; cost loads overlap ----
    float4 v4[4];
    {
        const float* Vg = g_V + (bh * NQ + t) * D_;
        #pragma unroll
        for (int j = 0; j < 4; j++) v4[j] = *(const float4*)&Vg[j * 4];
    }
    const float* cr0 = cost_mat + (b * NQ + r0) * NQ;
    const float* cr1 = cr0 + NQ;
    u64 cp[8];
    #pragma unroll
    for (int i = 0; i < 8; i++) {
        int c = i * 32 + lane;
        cp[i] = pk(__ldg(cr0 + c), __ldg(cr1 + c));
    }
    #pragma unroll
    for (int j = 0; j < 4; j++) *(float4*)&Vs[t][j * 4] = v4[j];
    __syncthreads();

    // ---- Phase 2: mixing MLP (abs half only; linear half analytic) ----
    u64 A2 = ABs[0], B2 = ABs[1];
    u64 s[8];
    #pragma unroll
    for (int i = 0; i < 8; i++)
        s[i] = fma2_(B2, cp[i], mul2_(A2, dp[i]));
    #pragma unroll 4
    for (int m = 0; m < 32; m++) {
        ulonglong2 w01 = *(const ulonglong2*)&mlpp[m][0];
        ulonglong2 w23 = *(const ulonglong2*)&mlpp[m][2];
        #pragma unroll
        for (int i = 0; i < 8; i++) {
            u64 t0 = fma2_(w01.x, dp[i], fma2_(w01.y, cp[i], w23.x));
            s[i] = fma2_(w23.y, t0 & ABSM, s[i]);
        }
    }

    // ---- Phase 3: softmax per row (pairs are (row0,row1)) ----
    float sc0[8], sc1[8];
    #pragma unroll
    for (int i = 0; i < 8; i++) upk(s[i], sc0[i], sc1[i]);
    float mx0 = sc0[0], mx1 = sc1[0];
    #pragma unroll
    for (int i = 1; i < 8; i++) { mx0 = fmaxf(mx0, sc0[i]); mx1 = fmaxf(mx1, sc1[i]); }
    #pragma unroll
    for (int o = 16; o; o >>= 1) {
        mx0 = fmaxf(mx0, __shfl_xor_sync(0xffffffffu, mx0, o));
        mx1 = fmaxf(mx1, __shfl_xor_sync(0xffffffffu, mx1, o));
    }
    float sum0 = 0.f, sum1 = 0.f;
    #pragma unroll
    for (int i = 0; i < 8; i++) {
        sc0[i] = __expf(sc0[i] - mx0); sum0 += sc0[i];
        sc1[i] = __expf(sc1[i] - mx1); sum1 += sc1[i];
    }
    #pragma unroll
    for (int o = 16; o; o >>= 1) {
        sum0 += __shfl_xor_sync(0xffffffffu, sum0, o);
        sum1 += __shfl_xor_sync(0xffffffffu, sum1, o);
    }
    float inv0 = 1.f / sum0, inv1 = 1.f / sum1;

    // ---- Phase 4: AV accumulation (packed over d pairs) ----
    u64 acc0[8], acc1[8];
    #pragma unroll
    for (int j = 0; j < 8; j++) { acc0[j] = 0ull; acc1[j] = 0ull; }
    #pragma unroll
    for (int i = 0; i < 8; i++) {
        int c = i * 32 + lane;
        u64 w0 = pk(sc0[i], sc0[i]);
        u64 w1 = pk(sc1[i], sc1[i]);
        #pragma unroll
        for (int j = 0; j < 4; j++) {
            float4 vv = *(const float4*)&Vs[c][j * 4];
            u64 vA = pk(vv.x, vv.y);
            u64 vB = pk(vv.z, vv.w);
            acc0[2 * j]     = fma2_(w0, vA, acc0[2 * j]);
            acc0[2 * j + 1] = fma2_(w0, vB, acc0[2 * j + 1]);
            acc1[2 * j]     = fma2_(w1, vA, acc1[2 * j]);
            acc1[2 * j + 1] = fma2_(w1, vB, acc1[2 * j + 1]);
        }
    }

    // ---- Phase 5: reduce-scatter epilogue ----
    int d0;
    float res0 = reduce16(acc0, lane, d0);
    int d1;
    float res1 = reduce16(acc1, lane, d1);
    if ((lane & 1) == 0) {
        out[(b * NQ + r0)     * (H_ * D_) + h * D_ + d0] = res0 * inv0;
        out[(b * NQ + r0 + 1) * (H_ * D_) + h * D_ + d1] = res1 * inv1;
    }
}

extern "C" void kernel_launch(void* const* d_in, const int* in_sizes, int n_in,
                              void* d_out, int out_size)
{
    const float* row_emb  = (const float*)d_in[0];
    const float* col_emb  = (const float*)d_in[1];
    const float* cost_mat = (const float*)d_in[2];
    const float* Wq       = (const float*)d_in[3];
    const float* Wk       = (const float*)d_in[4];
    const float* Wv       = (const float*)d_in[5];
    const float* m1w      = (const float*)d_in[6];
    const float* m1b      = (const float*)d_in[7];
    const float* m2w      = (const float*)d_in[8];
    // d_in[9] = mix2_bias: softmax-invariant, intentionally unused.
    float* out = (float*)d_out;

    dim3 gA(4, 16, 3);   // n-tiles x m-tiles x {Q,K,V}
    qkv_kernel<<<gA, 512>>>(row_emb, col_emb, Wq, Wk, Wv);

    dim3 gB(16, 16, 4);  // 16-row tiles x heads x batch
    attn_kernel<<<gB, 256>>>(cost_mat, m1w, m1b, m2w, out);
}